// round 1
// baseline (speedup 1.0000x reference)
#include <cuda_runtime.h>

// Problem constants
#define N_   32
#define C_   64
#define H_   112
#define W_   112
#define O_   128
#define KH_  3
#define KW_  3

// Tiling
#define OC_TILE  64     // output channels per block (8 oc-groups of 8)
#define H_TILE   8      // output rows per block
#define W_TILE   28     // output cols per block (4 threads x 7 px)
#define PX       7      // pixels per thread along W
#define IC_CHUNK 8      // input channels staged in smem per iteration

#define IN_ROWS  (H_TILE + 2)   // 10
#define IN_COLS  (W_TILE + 2)   // 30
#define W_PAD    (OC_TILE + 1)  // padded oc stride: conflict-free STS

__global__ __launch_bounds__(256, 2)
void conv3x3_ffma_kernel(const float* __restrict__ x,
                         const float* __restrict__ wgt,
                         const float* __restrict__ bias,
                         float* __restrict__ out)
{
    __shared__ float in_s[IC_CHUNK][IN_ROWS][IN_COLS];      // 9.6 KB
    __shared__ float w_s[IC_CHUNK][9][W_PAD];               // 18.7 KB

    const int t   = threadIdx.x;
    const int ocg = t >> 5;          // 0..7 : warp = one oc-group (weight broadcast)
    const int sp  = t & 31;
    const int th  = sp >> 2;         // 0..7 : output row within tile
    const int twt = sp & 3;          // 0..3 : 7-px column group

    const int wb = blockIdx.x;           // 0..3
    const int hb = blockIdx.y;           // 0..13
    const int z  = blockIdx.z;           // n*2 + ocb
    const int n   = z >> 1;
    const int oc0 = (z & 1) * OC_TILE;

    const int h0 = hb * H_TILE;
    const int w0 = wb * W_TILE;

    float acc[8][PX];
    #pragma unroll
    for (int j = 0; j < 8; ++j)
        #pragma unroll
        for (int p = 0; p < PX; ++p)
            acc[j][p] = 0.0f;

    const int n_ic_chunks = C_ / IC_CHUNK;   // 8

    for (int cc = 0; cc < n_ic_chunks; ++cc) {
        const int ic0 = cc * IC_CHUNK;

        __syncthreads();   // protect smem from previous iteration's readers

        // ---- stage input halo tile: IC_CHUNK x 10 x 30 = 2400 floats ----
        #pragma unroll
        for (int i = t; i < IC_CHUNK * IN_ROWS * IN_COLS; i += 256) {
            const int c   = i / (IN_ROWS * IN_COLS);
            const int r   = i % (IN_ROWS * IN_COLS);
            const int row = r / IN_COLS;
            const int col = r % IN_COLS;
            const int ih  = h0 + row - 1;
            const int iw  = w0 + col - 1;
            float v = 0.0f;
            if (ih >= 0 && ih < H_ && iw >= 0 && iw < W_)
                v = x[((n * C_ + ic0 + c) * H_ + ih) * W_ + iw];
            in_s[c][row][col] = v;
        }

        // ---- stage weights: 64 oc x IC_CHUNK ic x 9 = 4608 floats ----
        // global runs of 72 contiguous floats per oc (coalesced);
        // smem layout [ic][kk][oc] with padded oc stride (no STS conflicts)
        #pragma unroll
        for (int i = t; i < OC_TILE * IC_CHUNK * 9; i += 256) {
            const int o  = i / (IC_CHUNK * 9);
            const int r  = i % (IC_CHUNK * 9);        // = c*9 + kk
            const int c  = r / 9;
            const int kk = r % 9;
            w_s[c][kk][o] = wgt[(oc0 + o) * (C_ * 9) + ic0 * 9 + r];
        }

        __syncthreads();

        // ---- compute ----
        #pragma unroll 1
        for (int c = 0; c < IC_CHUNK; ++c) {
            #pragma unroll
            for (int kh = 0; kh < KH_; ++kh) {
                // 9 contiguous input values cover 7 px + 2 halo; reused over kw
                float rin[PX + 2];
                const float* src = &in_s[c][th + kh][twt * PX];
                #pragma unroll
                for (int p = 0; p < PX + 2; ++p) rin[p] = src[p];

                #pragma unroll
                for (int kw = 0; kw < KW_; ++kw) {
                    float wr[8];
                    const float* wsrc = &w_s[c][kh * 3 + kw][ocg * 8];
                    #pragma unroll
                    for (int j = 0; j < 8; ++j) wr[j] = wsrc[j];   // warp-broadcast LDS

                    #pragma unroll
                    for (int j = 0; j < 8; ++j)
                        #pragma unroll
                        for (int p = 0; p < PX; ++p)
                            acc[j][p] = fmaf(wr[j], rin[p + kw], acc[j][p]);
                }
            }
        }
    }

    // ---- epilogue: bias + store ----
    const int oh = h0 + th;
    const int ow0 = w0 + twt * PX;
    #pragma unroll
    for (int j = 0; j < 8; ++j) {
        const int oc = oc0 + ocg * 8 + j;
        const float b = bias[oc];
        float* dst = &out[((n * O_ + oc) * H_ + oh) * W_ + ow0];
        #pragma unroll
        for (int p = 0; p < PX; ++p)
            dst[p] = acc[j][p] + b;
    }
}

extern "C" void kernel_launch(void* const* d_in, const int* in_sizes, int n_in,
                              void* d_out, int out_size)
{
    const float* x    = (const float*)d_in[0];
    const float* wgt  = (const float*)d_in[1];
    const float* bias = (const float*)d_in[2];
    float* out        = (float*)d_out;

    dim3 grid(W_ / W_TILE, H_ / H_TILE, N_ * (O_ / OC_TILE));  // (4, 14, 64)
    conv3x3_ffma_kernel<<<grid, 256>>>(x, wgt, bias, out);
}

// round 2
// speedup vs baseline: 1.2966x; 1.2966x over previous
#include <cuda_runtime.h>

// Problem constants
#define N_   32
#define C_   64
#define H_   112
#define W_   112
#define O_   128
#define KH_  3
#define KW_  3

// Tiling
#define OC_TILE  64     // output channels per block (8 oc-groups of 8)
#define H_TILE   8      // output rows per block
#define W_TILE   28     // output cols per block (4 threads x 7 px)
#define PX       7      // pixels per thread along W
#define IC_CHUNK 8      // input channels staged in smem per iteration

#define IN_ROWS  (H_TILE + 2)   // 10
#define IN_COLS  (W_TILE + 2)   // 30
#define W_PAD    (OC_TILE + 2)  // 66: even -> 8B-aligned LDS.64 on packed weights

typedef unsigned long long u64;

__device__ __forceinline__ u64 dupf(float v) {
    u64 r;
    asm("mov.b64 %0, {%1, %1};" : "=l"(r) : "r"(__float_as_uint(v)));
    return r;
}

__device__ __forceinline__ void fma2(u64& acc, u64 a, u64 b) {
    asm("fma.rn.f32x2 %0, %1, %2, %0;" : "+l"(acc) : "l"(a), "l"(b));
}

__device__ __forceinline__ float lo32(u64 v) { return __uint_as_float((unsigned)v); }
__device__ __forceinline__ float hi32(u64 v) { return __uint_as_float((unsigned)(v >> 32)); }

__global__ __launch_bounds__(256, 2)
void conv3x3_ffma2_kernel(const float* __restrict__ x,
                          const float* __restrict__ wgt,
                          const float* __restrict__ bias,
                          float* __restrict__ out)
{
    __shared__ float in_s[IC_CHUNK][IN_ROWS][IN_COLS];      // 9.6 KB
    __shared__ float w_s[IC_CHUNK][9][W_PAD];               // 19.0 KB

    const int t   = threadIdx.x;
    const int ocg = t >> 5;          // 0..7 : warp = one oc-group (weight broadcast)
    const int sp  = t & 31;
    const int th  = sp >> 2;         // 0..7 : output row within tile
    const int twt = sp & 3;          // 0..3 : 7-px column group

    const int wb = blockIdx.x;           // 0..3
    const int hb = blockIdx.y;           // 0..13
    const int z  = blockIdx.z;           // n*2 + ocb
    const int n   = z >> 1;
    const int oc0 = (z & 1) * OC_TILE;

    const int h0 = hb * H_TILE;
    const int w0 = wb * W_TILE;

    // acc2[jj][p]: jj = oc pair (4 pairs = 8 oc), p = pixel. lo = oc 2jj, hi = oc 2jj+1
    u64 acc2[4][PX];
    #pragma unroll
    for (int jj = 0; jj < 4; ++jj)
        #pragma unroll
        for (int p = 0; p < PX; ++p)
            acc2[jj][p] = 0ull;

    const int n_ic_chunks = C_ / IC_CHUNK;   // 8

    for (int cc = 0; cc < n_ic_chunks; ++cc) {
        const int ic0 = cc * IC_CHUNK;

        __syncthreads();   // protect smem from previous iteration's readers

        // ---- stage input halo tile: IC_CHUNK x 10 x 30 = 2400 floats ----
        #pragma unroll
        for (int i = t; i < IC_CHUNK * IN_ROWS * IN_COLS; i += 256) {
            const int c   = i / (IN_ROWS * IN_COLS);
            const int r   = i % (IN_ROWS * IN_COLS);
            const int row = r / IN_COLS;
            const int col = r % IN_COLS;
            const int ih  = h0 + row - 1;
            const int iw  = w0 + col - 1;
            float v = 0.0f;
            if (ih >= 0 && ih < H_ && iw >= 0 && iw < W_)
                v = x[((n * C_ + ic0 + c) * H_ + ih) * W_ + iw];
            in_s[c][row][col] = v;
        }

        // ---- stage weights: 64 oc x IC_CHUNK ic x 9 = 4608 floats ----
        #pragma unroll
        for (int i = t; i < OC_TILE * IC_CHUNK * 9; i += 256) {
            const int o  = i / (IC_CHUNK * 9);
            const int r  = i % (IC_CHUNK * 9);        // = c*9 + kk
            const int c  = r / 9;
            const int kk = r % 9;
            w_s[c][kk][o] = wgt[(oc0 + o) * (C_ * 9) + ic0 * 9 + r];
        }

        __syncthreads();

        // ---- compute ----
        #pragma unroll 1
        for (int c = 0; c < IC_CHUNK; ++c) {
            #pragma unroll
            for (int kh = 0; kh < KH_; ++kh) {
                // 9 contiguous input values cover 7 px + 2 halo; duplicated into
                // both f32x2 lanes once, reused across kw and all 4 oc-pairs.
                u64 rr[PX + 2];
                const float* src = &in_s[c][th + kh][twt * PX];
                #pragma unroll
                for (int p = 0; p < PX + 2; ++p) rr[p] = dupf(src[p]);

                #pragma unroll
                for (int kw = 0; kw < KW_; ++kw) {
                    // packed weight pairs: aligned 8B LDS from smem (warp-broadcast)
                    u64 w2[4];
                    const u64* wsrc = reinterpret_cast<const u64*>(&w_s[c][kh * 3 + kw][ocg * 8]);
                    #pragma unroll
                    for (int jj = 0; jj < 4; ++jj) w2[jj] = wsrc[jj];

                    #pragma unroll
                    for (int jj = 0; jj < 4; ++jj)
                        #pragma unroll
                        for (int p = 0; p < PX; ++p)
                            fma2(acc2[jj][p], w2[jj], rr[p + kw]);
                }
            }
        }
    }

    // ---- epilogue: bias + store ----
    const int oh  = h0 + th;
    const int ow0 = w0 + twt * PX;
    #pragma unroll
    for (int jj = 0; jj < 4; ++jj) {
        const int oc_lo = oc0 + ocg * 8 + 2 * jj;
        const float b_lo = bias[oc_lo];
        const float b_hi = bias[oc_lo + 1];
        float* dst_lo = &out[((n * O_ + oc_lo) * H_ + oh) * W_ + ow0];
        float* dst_hi = dst_lo + H_ * W_;
        #pragma unroll
        for (int p = 0; p < PX; ++p) {
            dst_lo[p] = lo32(acc2[jj][p]) + b_lo;
            dst_hi[p] = hi32(acc2[jj][p]) + b_hi;
        }
    }
}

extern "C" void kernel_launch(void* const* d_in, const int* in_sizes, int n_in,
                              void* d_out, int out_size)
{
    const float* x    = (const float*)d_in[0];
    const float* wgt  = (const float*)d_in[1];
    const float* bias = (const float*)d_in[2];
    float* out        = (float*)d_out;

    dim3 grid(W_ / W_TILE, H_ / H_TILE, N_ * (O_ / OC_TILE));  // (4, 14, 64)
    conv3x3_ffma2_kernel<<<grid, 256>>>(x, wgt, bias, out);
}

// round 4
// speedup vs baseline: 2.3025x; 1.7758x over previous
#include <cuda_runtime.h>
#include <cstdint>

// x[32,64,112,112] (*) w[128,64,3,3] + b[128] -> out[32,128,112,112], pad=1, stride=1
// Implicit GEMM: D[128 oc][pix] = W[128][576] x im2col[576][pix]
// CTA tile: M=128, N=128 pixels, K-chunks of 32. mma.sync m16n8k8 tf32 (base PTX, sm_80+).

#define KTOT  576
#define KCH   32
#define NCHUNK 18
#define STR   36                 // smem row stride (floats): conflict-free frags + STS.128
#define ABUF  (128*STR)          // floats per buffer (A or B)
#define SMEM_BYTES (4*ABUF*4)    // 73728

__device__ __forceinline__ uint32_t tf32c(float f) {
    uint32_t u; asm("cvt.rna.tf32.f32 %0, %1;" : "=r"(u) : "f"(f)); return u;
}

__global__ __launch_bounds__(256, 2)
void conv3x3_tf32_hmma(const float* __restrict__ x,
                       const float* __restrict__ w,
                       const float* __restrict__ bias,
                       float* __restrict__ out)
{
    extern __shared__ uint32_t sm[];
    uint32_t* const Abase = sm;              // A[buf][oc=128][k=32] stride 36
    uint32_t* const Bbase = sm + 2 * ABUF;   // B[buf][px=128][k=32] stride 36

    const int tid = threadIdx.x;
    const int lid = tid & 31;
    const int wid = tid >> 5;
    const int warp_m = wid & 3;          // 4 warps over M (32 oc each)
    const int warp_n = wid >> 2;         // 2 warps over N (64 px each)
    const int g = lid >> 2, q = lid & 3; // mma fragment coords

    // ---- staging coords (fixed per thread) ----
    const int oc_a = tid & 127;          // A: this thread's oc row
    const int qa0  = tid >> 7;           // A: k-quad parity
    const int qb   = tid & 7;            // B: k-quad
    const int px0  = tid >> 3;           // B: base pixel (0..31)

    int pn[4], poh[4], pw[4];            // pixel decompositions (4 px per thread)
    #pragma unroll
    for (int it = 0; it < 4; ++it) {
        const int P = blockIdx.x * 128 + px0 + 32 * it;
        pn[it] = P / 12544;
        const int rem = P - pn[it] * 12544;
        poh[it] = rem / 112;
        pw[it]  = rem - poh[it] * 112;
    }

    float acc[2][8][4];
    #pragma unroll
    for (int mt = 0; mt < 2; ++mt)
        #pragma unroll
        for (int nt = 0; nt < 8; ++nt)
            #pragma unroll
            for (int e = 0; e < 4; ++e) acc[mt][nt][e] = 0.0f;

    auto stage = [&](int c) {
        const int b = c & 1, k0 = c * KCH;
        uint32_t* const As = Abase + b * ABUF;
        uint32_t* const Bs = Bbase + b * ABUF;

        // A: weights, coalesced float4 LDG, conflict-free STS.128
        #pragma unroll
        for (int it = 0; it < 4; ++it) {
            const int qa = qa0 + 2 * it;
            const float4 v = *reinterpret_cast<const float4*>(w + oc_a * KTOT + k0 + qa * 4);
            uint4 t;
            t.x = tf32c(v.x); t.y = tf32c(v.y); t.z = tf32c(v.z); t.w = tf32c(v.w);
            *reinterpret_cast<uint4*>(As + oc_a * STR + qa * 4) = t;
        }

        // B: im2col gather. k -> (ic,kh,kw) fixed per thread per chunk.
        int ick[4], khk[4], kwk[4];
        #pragma unroll
        for (int j = 0; j < 4; ++j) {
            const int k = k0 + qb * 4 + j;
            ick[j] = k / 9;
            const int r = k - ick[j] * 9;
            khk[j] = r / 3;
            kwk[j] = r - khk[j] * 3;
        }
        #pragma unroll
        for (int it = 0; it < 4; ++it) {
            uint32_t tv[4];
            #pragma unroll
            for (int j = 0; j < 4; ++j) {
                const int ih = poh[it] + khk[j] - 1;
                const int iw = pw[it]  + kwk[j] - 1;
                float v = 0.0f;
                if (ih >= 0 && ih < 112 && iw >= 0 && iw < 112)
                    v = x[((pn[it] * 64 + ick[j]) * 112 + ih) * 112 + iw];
                tv[j] = tf32c(v);
            }
            uint4 t = make_uint4(tv[0], tv[1], tv[2], tv[3]);
            *reinterpret_cast<uint4*>(Bs + (px0 + 32 * it) * STR + qb * 4) = t;
        }
    };

    auto compute = [&](int c) {
        const int b = c & 1;
        const uint32_t* const As = Abase + b * ABUF;
        const uint32_t* const Bs = Bbase + b * ABUF;
        #pragma unroll
        for (int s = 0; s < 4; ++s) {
            const int ks = s * 8;
            uint32_t a[2][4];
            #pragma unroll
            for (int mt = 0; mt < 2; ++mt) {
                const uint32_t* ap = As + (warp_m * 32 + mt * 16 + g) * STR + ks + q;
                a[mt][0] = ap[0];
                a[mt][1] = ap[8 * STR];
                a[mt][2] = ap[4];
                a[mt][3] = ap[8 * STR + 4];
            }
            #pragma unroll
            for (int nt = 0; nt < 8; ++nt) {
                const uint32_t* bp = Bs + (warp_n * 64 + nt * 8 + g) * STR + ks + q;
                const uint32_t b0 = bp[0], b1 = bp[4];
                #pragma unroll
                for (int mt = 0; mt < 2; ++mt) {
                    float* d = acc[mt][nt];
                    asm volatile(
                        "mma.sync.aligned.m16n8k8.row.col.f32.tf32.tf32.f32 "
                        "{%0,%1,%2,%3}, {%4,%5,%6,%7}, {%8,%9}, {%0,%1,%2,%3};"
                        : "+f"(d[0]), "+f"(d[1]), "+f"(d[2]), "+f"(d[3])
                        : "r"(a[mt][0]), "r"(a[mt][1]), "r"(a[mt][2]), "r"(a[mt][3]),
                          "r"(b0), "r"(b1));
                }
            }
        }
    };

    stage(0);
    __syncthreads();
    for (int c = 0; c < NCHUNK; ++c) {
        if (c + 1 < NCHUNK) stage(c + 1);
        compute(c);
        __syncthreads();
    }

    // ---- epilogue: cols are even pixels -> (col, col+1) same output row, float2 ----
    #pragma unroll
    for (int mt = 0; mt < 2; ++mt) {
        const int oc0 = warp_m * 32 + mt * 16 + g;
        const float bv0 = bias[oc0];
        const float bv1 = bias[oc0 + 8];
        #pragma unroll
        for (int nt = 0; nt < 8; ++nt) {
            const int col = warp_n * 64 + nt * 8 + 2 * q;
            const int P = blockIdx.x * 128 + col;
            const int n = P / 12544;
            const int rem = P - n * 12544;
            const int oh = rem / 112;
            const int ow = rem - oh * 112;      // even -> ow+1 same row
            float2 v0, v1;
            v0.x = acc[mt][nt][0] + bv0; v0.y = acc[mt][nt][1] + bv0;
            v1.x = acc[mt][nt][2] + bv1; v1.y = acc[mt][nt][3] + bv1;
            float* base = out + (((size_t)n * 128 + oc0) * 112 + oh) * 112 + ow;
            *reinterpret_cast<float2*>(base) = v0;
            *reinterpret_cast<float2*>(base + 8 * 112 * 112) = v1;
        }
    }
}

extern "C" void kernel_launch(void* const* d_in, const int* in_sizes, int n_in,
                              void* d_out, int out_size)
{
    const float* x    = (const float*)d_in[0];
    const float* wgt  = (const float*)d_in[1];
    const float* bias = (const float*)d_in[2];
    float* out        = (float*)d_out;

    cudaFuncSetAttribute(conv3x3_tf32_hmma,
                         cudaFuncAttributeMaxDynamicSharedMemorySize, SMEM_BYTES);
    const int grid = (32 * 112 * 112) / 128;   // 3136
    conv3x3_tf32_hmma<<<grid, 256, SMEM_BYTES>>>(x, wgt, bias, out);
}

// round 5
// speedup vs baseline: 3.1151x; 1.3529x over previous
#include <cuda_runtime.h>
#include <cstdint>

// x[32,64,112,112] (*) w[128,64,3,3] + b[128] -> out[32,128,112,112], pad=1, stride=1
// Implicit GEMM: D[128 oc][pix] = W[128][576] x im2col[576][pix]
// CTA tile M=128, N=128 px, K-chunk 32. mma.sync m16n8k8 tf32 + ldmatrix (base PTX).

#define KTOT  576
#define NCHUNK 18
#define STR   36                 // smem row stride (words): conflict-free LDSM/STS
#define BUF   (128*STR)          // words per A (or B) buffer
#define SMEM_BYTES (4*BUF*4)     // 73728

__device__ __forceinline__ uint32_t tf32c(float f) {
    uint32_t u; asm("cvt.rna.tf32.f32 %0, %1;" : "=r"(u) : "f"(f)); return u;
}
__device__ __forceinline__ void ldsm4(uint32_t* r, uint32_t addr) {
    asm volatile("ldmatrix.sync.aligned.m8n8.x4.shared.b16 {%0,%1,%2,%3}, [%4];"
                 : "=r"(r[0]), "=r"(r[1]), "=r"(r[2]), "=r"(r[3]) : "r"(addr));
}

__global__ __launch_bounds__(256, 2)
void conv3x3_tf32_hmma2(const float* __restrict__ x,
                        const float* __restrict__ w,
                        const float* __restrict__ bias,
                        float* __restrict__ out)
{
    extern __shared__ uint32_t sm[];
    uint32_t* const Abase = sm;              // A[buf][oc=128][k=32] stride STR
    uint32_t* const Bbase = sm + 2 * BUF;    // B[buf][px=128][k=32] stride STR

    const int tid = threadIdx.x;
    const int lid = tid & 31;
    const int wid = tid >> 5;
    const int warp_m = wid & 3;              // 32 oc per warp
    const int warp_n = wid >> 2;             // 64 px per warp

    // ---- per-thread pixel decomposition for B staging (fixed across chunks) ----
    int pn[4], poh[4], pow_[4];
    #pragma unroll
    for (int it = 0; it < 4; ++it) {
        const int P = blockIdx.x * 128 + lid + 32 * it;
        pn[it] = P / 12544;
        const int rem = P - pn[it] * 12544;
        poh[it] = rem / 112;
        pow_[it] = rem - poh[it] * 112;
    }

    // ---- ldmatrix per-thread smem addresses (byte, shared space) ----
    const uint32_t smem_u32 = (uint32_t)__cvta_generic_to_shared(sm);
    const int rowsel = lid & 15;
    const int colsel = (lid >> 4) * 4;       // tf32 col offset (words)
    const uint32_t aAddr = smem_u32 + 4 * ((warp_m * 32 + rowsel) * STR + colsel);
    const uint32_t bAddr = smem_u32 + 4 * (2 * BUF + (warp_n * 64 + rowsel) * STR + colsel);

    float acc[2][8][4];
    #pragma unroll
    for (int mt = 0; mt < 2; ++mt)
        #pragma unroll
        for (int nt = 0; nt < 8; ++nt)
            #pragma unroll
            for (int e = 0; e < 4; ++e) acc[mt][nt][e] = 0.0f;

    auto stage = [&](int c) {
        const int b = c & 1, k0 = c * 32;
        uint32_t* const As = Abase + b * BUF;
        uint32_t* const Bs = Bbase + b * BUF;

        // A: warp w covers oc rows [w*16, w*16+16). Lanes sweep k within a row
        // (rows are 128B contiguous in gmem -> coalesced), STS.128 conflict-free.
        {
            const int q = lid & 7;                       // k-quad within row
            const int rsub = lid >> 3;                   // 0..3
            #pragma unroll
            for (int iter = 0; iter < 4; ++iter) {
                const int row = wid * 16 + iter * 4 + rsub;
                const float4 v = *reinterpret_cast<const float4*>(w + row * KTOT + k0 + q * 4);
                uint4 t;
                t.x = tf32c(v.x); t.y = tf32c(v.y); t.z = tf32c(v.z); t.w = tf32c(v.w);
                *reinterpret_cast<uint4*>(As + row * STR + q * 4) = t;
            }
        }

        // B: warp w owns k-quad w; lanes sweep 32 consecutive pixels (coalesced LDG).
        {
            int ic[4], kh[4], kw[4];
            #pragma unroll
            for (int j = 0; j < 4; ++j) {
                const int k = k0 + wid * 4 + j;
                ic[j] = k / 9;
                const int r = k - ic[j] * 9;
                kh[j] = r / 3;
                kw[j] = r - kh[j] * 3;
            }
            #pragma unroll
            for (int it = 0; it < 4; ++it) {
                uint32_t tv[4];
                #pragma unroll
                for (int j = 0; j < 4; ++j) {
                    const int ih = poh[it] + kh[j] - 1;
                    const int iw = pow_[it] + kw[j] - 1;
                    float v = 0.0f;
                    if (ih >= 0 && ih < 112 && iw >= 0 && iw < 112)
                        v = x[((pn[it] * 64 + ic[j]) * 112 + ih) * 112 + iw];
                    tv[j] = tf32c(v);
                }
                *reinterpret_cast<uint4*>(Bs + (lid + 32 * it) * STR + wid * 4) =
                    make_uint4(tv[0], tv[1], tv[2], tv[3]);
            }
        }
    };

    auto compute = [&](int c) {
        const uint32_t boff = (c & 1) ? (uint32_t)(BUF * 4) : 0u;
        #pragma unroll
        for (int s = 0; s < 4; ++s) {
            uint32_t a[2][4];
            #pragma unroll
            for (int mt = 0; mt < 2; ++mt)
                ldsm4(a[mt], aAddr + boff + mt * (16 * STR * 4) + s * 32);

            uint32_t bf[4][4];
            #pragma unroll
            for (int np = 0; np < 4; ++np)
                ldsm4(bf[np], bAddr + boff + np * (16 * STR * 4) + s * 32);

            #pragma unroll
            for (int np = 0; np < 4; ++np)
                #pragma unroll
                for (int half = 0; half < 2; ++half) {
                    const int nt = 2 * np + half;
                    const uint32_t b0 = half ? bf[np][1] : bf[np][0];
                    const uint32_t b1 = half ? bf[np][3] : bf[np][2];
                    #pragma unroll
                    for (int mt = 0; mt < 2; ++mt) {
                        float* d = acc[mt][nt];
                        asm volatile(
                            "mma.sync.aligned.m16n8k8.row.col.f32.tf32.tf32.f32 "
                            "{%0,%1,%2,%3}, {%4,%5,%6,%7}, {%8,%9}, {%0,%1,%2,%3};"
                            : "+f"(d[0]), "+f"(d[1]), "+f"(d[2]), "+f"(d[3])
                            : "r"(a[mt][0]), "r"(a[mt][1]), "r"(a[mt][2]), "r"(a[mt][3]),
                              "r"(b0), "r"(b1));
                    }
                }
        }
    };

    stage(0);
    __syncthreads();
    for (int c = 0; c < NCHUNK; ++c) {
        if (c + 1 < NCHUNK) stage(c + 1);
        compute(c);
        __syncthreads();
    }

    // ---- epilogue: cols are even pixels -> (col, col+1) same output row ----
    const int g = lid >> 2, q = lid & 3;
    #pragma unroll
    for (int mt = 0; mt < 2; ++mt) {
        const int oc0 = warp_m * 32 + mt * 16 + g;
        const float bv0 = bias[oc0];
        const float bv1 = bias[oc0 + 8];
        #pragma unroll
        for (int nt = 0; nt < 8; ++nt) {
            const int col = warp_n * 64 + nt * 8 + 2 * q;
            const int P = blockIdx.x * 128 + col;
            const int n = P / 12544;
            const int rem = P - n * 12544;
            const int oh = rem / 112;
            const int ow = rem - oh * 112;       // even -> ow+1 same row
            float2 v0, v1;
            v0.x = acc[mt][nt][0] + bv0; v0.y = acc[mt][nt][1] + bv0;
            v1.x = acc[mt][nt][2] + bv1; v1.y = acc[mt][nt][3] + bv1;
            float* base = out + (((size_t)n * 128 + oc0) * 112 + oh) * 112 + ow;
            *reinterpret_cast<float2*>(base) = v0;
            *reinterpret_cast<float2*>(base + 8 * 112 * 112) = v1;
        }
    }
}

extern "C" void kernel_launch(void* const* d_in, const int* in_sizes, int n_in,
                              void* d_out, int out_size)
{
    const float* x    = (const float*)d_in[0];
    const float* wgt  = (const float*)d_in[1];
    const float* bias = (const float*)d_in[2];
    float* out        = (float*)d_out;

    cudaFuncSetAttribute(conv3x3_tf32_hmma2,
                         cudaFuncAttributeMaxDynamicSharedMemorySize, SMEM_BYTES);
    const int grid = (32 * 112 * 112) / 128;   // 3136
    conv3x3_tf32_hmma2<<<grid, 256, SMEM_BYTES>>>(x, wgt, bias, out);
}

// round 6
// speedup vs baseline: 3.5519x; 1.1402x over previous
#include <cuda_runtime.h>
#include <cstdint>

// x[32,64,112,112] (*) w[128,64,3,3] + b[128] -> out[32,128,112,112], pad=1
// Conv as 9 shifted GEMMs: per CTA (n, oh): D[128 oc][112 px], K = 2 ic-halves x 9 passes x k32.
// B fragments read straight from a raw channels-last input tile via ldmatrix (no im2col).

#define KTOT 576
#define STR  36                         // smem row stride (words)
#define RAW_WORDS  (3*114*STR)          // 12312
#define ABUF_WORDS (128*STR)            // 4608
#define SMEM_BYTES ((RAW_WORDS + 2*ABUF_WORDS)*4)   // 86112

__device__ uint32_t Wt[2*9*128*32];     // [half][pass][oc][icl], tf32

__device__ __forceinline__ uint32_t tf32c(float f) {
    uint32_t u; asm("cvt.rna.tf32.f32 %0, %1;" : "=r"(u) : "f"(f)); return u;
}
__device__ __forceinline__ void ldsm4(uint32_t* r, uint32_t addr) {
    asm volatile("ldmatrix.sync.aligned.m8n8.x4.shared.b16 {%0,%1,%2,%3}, [%4];"
                 : "=r"(r[0]), "=r"(r[1]), "=r"(r[2]), "=r"(r[3]) : "r"(addr));
}
__device__ __forceinline__ void ldsm2(uint32_t* r, uint32_t addr) {
    asm volatile("ldmatrix.sync.aligned.m8n8.x2.shared.b16 {%0,%1}, [%2];"
                 : "=r"(r[0]), "=r"(r[1]) : "r"(addr));
}
__device__ __forceinline__ void mma8(float* d, const uint32_t* a, uint32_t b0, uint32_t b1) {
    asm volatile(
        "mma.sync.aligned.m16n8k8.row.col.f32.tf32.tf32.f32 "
        "{%0,%1,%2,%3}, {%4,%5,%6,%7}, {%8,%9}, {%0,%1,%2,%3};"
        : "+f"(d[0]), "+f"(d[1]), "+f"(d[2]), "+f"(d[3])
        : "r"(a[0]), "r"(a[1]), "r"(a[2]), "r"(a[3]), "r"(b0), "r"(b1));
}

__global__ void prep_weights(const float* __restrict__ w) {
    const int i = blockIdx.x * 256 + threadIdx.x;     // 73728 total
    const int icl = i & 31;
    const int t   = i >> 5;
    const int oc  = t & 127;
    const int hr  = t >> 7;            // h*9 + r
    const int r   = hr % 9;
    const int h   = hr / 9;
    Wt[i] = tf32c(w[oc * KTOT + (h * 32 + icl) * 9 + r]);
}

__global__ __launch_bounds__(256, 2)
void conv3x3_shift(const float* __restrict__ x,
                   const float* __restrict__ bias,
                   float* __restrict__ out)
{
    extern __shared__ uint32_t sm[];
    uint32_t* const Raw = sm;                    // [3*114 px][36] (32 ic + pad)
    uint32_t* const Asm = sm + RAW_WORDS;        // 2 x [128 oc][36]

    const int tid = threadIdx.x;
    const int lid = tid & 31;
    const int wid = tid >> 5;
    const int wm  = wid & 3;                     // 32 oc per warp
    const int wn  = wid >> 2;                    // 56 px per warp

    const int bz = blockIdx.x;
    const int n  = bz / 112;
    const int oh = bz - n * 112;

    const uint32_t smem_b = (uint32_t)__cvta_generic_to_shared(sm);
    // per-thread ldmatrix offsets (bytes)
    const uint32_t aOff  = smem_b + RAW_WORDS * 4 +
                           4 * ((wm * 32 + (lid & 15)) * STR + ((lid >> 4) << 2));
    const uint32_t bOff4 = 4 * ((lid & 15) * STR + ((lid >> 4) << 2));
    const uint32_t bOff2 = 4 * ((lid & 7) * STR + (((lid >> 3) & 1) << 2));

    float acc[2][7][4];
    #pragma unroll
    for (int mt = 0; mt < 2; ++mt)
        #pragma unroll
        for (int nt = 0; nt < 7; ++nt)
            #pragma unroll
            for (int e = 0; e < 4; ++e) acc[mt][nt][e] = 0.0f;

    // ---- stage A pass tile from pre-transposed weights (fully coalesced) ----
    auto stage_A = [&](int h, int r, int buf) {
        const uint32_t* src = Wt + (h * 9 + r) * 4096;          // [128][32]
        uint32_t* dst = Asm + buf * ABUF_WORDS;
        const int q = tid & 7, ocr = tid >> 3;
        #pragma unroll
        for (int it = 0; it < 4; ++it) {
            const int oc = it * 32 + ocr;
            const uint4 v = *reinterpret_cast<const uint4*>(src + oc * 32 + q * 4);
            *reinterpret_cast<uint4*>(dst + oc * STR + q * 4) = v;
        }
    };

    // ---- stage raw input tile for ic-half h: [3 rows][114 cols][32 ic] ----
    auto stage_raw = [&](int h) {
        const float* xb = x + ((size_t)(n * 64 + h * 32) * 112) * 112;
        for (int idx = tid; idx < 2736; idx += 256) {     // 24 combos x 114 cols
            const int combo = idx / 114;
            const int col   = idx - combo * 114;
            const int row   = combo >> 3;                 // 0..2
            const int icq   = combo & 7;                  // ic quad
            const int ih = oh - 1 + row;
            const int iw = col - 1;
            uint4 t;
            if (ih >= 0 && ih < 112 && iw >= 0 && iw < 112) {
                const float* p = xb + (size_t)icq * 4 * 12544 + ih * 112 + iw;
                t.x = tf32c(p[0]);
                t.y = tf32c(p[12544]);
                t.z = tf32c(p[25088]);
                t.w = tf32c(p[37632]);
            } else {
                t.x = t.y = t.z = t.w = 0u;
            }
            *reinterpret_cast<uint4*>(Raw + (row * 114 + col) * STR + icq * 4) = t;
        }
    };

    // ---- one (kh,kw) GEMM pass, K=32, from shifted raw-tile base ----
    auto compute = [&](int r, int buf) {
        const int kh = r / 3, kw = r - 3 * kh;
        const uint32_t b4 = smem_b + 4 * ((kh * 114 + kw + wn * 56) * STR) + bOff4;
        const uint32_t b2 = smem_b + 4 * ((kh * 114 + kw + wn * 56 + 48) * STR) + bOff2;
        const uint32_t aB = aOff + buf * (ABUF_WORDS * 4);
        #pragma unroll
        for (int s = 0; s < 4; ++s) {
            uint32_t a0[4], a1[4];
            ldsm4(a0, aB + s * 32);
            ldsm4(a1, aB + 16 * STR * 4 + s * 32);
            #pragma unroll
            for (int np = 0; np < 3; ++np) {
                uint32_t bf[4];
                ldsm4(bf, b4 + np * (16 * STR * 4) + s * 32);
                #pragma unroll
                for (int half = 0; half < 2; ++half) {
                    const int nt = np * 2 + half;
                    mma8(acc[0][nt], a0, bf[half], bf[2 + half]);
                    mma8(acc[1][nt], a1, bf[half], bf[2 + half]);
                }
            }
            uint32_t bg[2];
            ldsm2(bg, b2 + s * 32);
            mma8(acc[0][6], a0, bg[0], bg[1]);
            mma8(acc[1][6], a1, bg[0], bg[1]);
        }
    };

    for (int h = 0; h < 2; ++h) {
        stage_raw(h);
        stage_A(h, 0, 0);
        __syncthreads();
        for (int r = 0; r < 9; ++r) {
            if (r < 8) stage_A(h, r + 1, (r + 1) & 1);   // overlap next-pass A LDG
            compute(r, r & 1);
            __syncthreads();
        }
    }

    // ---- epilogue ----
    const int g = lid >> 2, q = lid & 3;
    #pragma unroll
    for (int mt = 0; mt < 2; ++mt) {
        const int oc0 = wm * 32 + mt * 16 + g;
        const float bv0 = bias[oc0];
        const float bv1 = bias[oc0 + 8];
        #pragma unroll
        for (int nt = 0; nt < 7; ++nt) {
            const int col = wn * 56 + nt * 8 + 2 * q;
            float2 v0, v1;
            v0.x = acc[mt][nt][0] + bv0; v0.y = acc[mt][nt][1] + bv0;
            v1.x = acc[mt][nt][2] + bv1; v1.y = acc[mt][nt][3] + bv1;
            float* base = out + (((size_t)n * 128 + oc0) * 112 + oh) * 112 + col;
            *reinterpret_cast<float2*>(base) = v0;
            *reinterpret_cast<float2*>(base + 8 * 112 * 112) = v1;
        }
    }
}

extern "C" void kernel_launch(void* const* d_in, const int* in_sizes, int n_in,
                              void* d_out, int out_size)
{
    const float* x    = (const float*)d_in[0];
    const float* wgt  = (const float*)d_in[1];
    const float* bias = (const float*)d_in[2];
    float* out        = (float*)d_out;

    prep_weights<<<288, 256>>>(wgt);   // 73728 elems, one-time re-layout + tf32

    cudaFuncSetAttribute(conv3x3_shift,
                         cudaFuncAttributeMaxDynamicSharedMemorySize, SMEM_BYTES);
    conv3x3_shift<<<32 * 112, 256, SMEM_BYTES>>>(x, bias, out);
}